// round 1
// baseline (speedup 1.0000x reference)
#include <cuda_runtime.h>
#include <cuda_bf16.h>
#include <cstdint>

// Problem constants
#define BATCH 32
#define C     192
#define HW    3136            // 56*56
#define CHW   602112          // C*HW
#define T_STEPS 96
#define NSLICE 64             // K-slices for gram GEMM (2 per batch image)
#define KC    1568            // K per slice (HW/2)
#define KT    32              // k-tile
#define STRIDE 68             // padded smem row stride (multiple of 4 for float4)

// Static device scratch (no allocations allowed)
__device__ float g_partial[NSLICE * 6 * 64 * 64];   // 6 MB
__device__ float g_G[C * C];
__device__ float g_D2[C * C];
__device__ int   g_v1[T_STEPS];
__device__ int   g_v2[T_STEPS];

__constant__ int c_TA[6] = {0, 0, 0, 1, 1, 2};
__constant__ int c_TB[6] = {0, 1, 2, 1, 2, 2};

// ---------------------------------------------------------------------------
// Kernel 1: partial Gram.  Block (ti, s): 64x64 tile ti over K-slice s.
// ---------------------------------------------------------------------------
__global__ __launch_bounds__(256) void gram_kernel(const float* __restrict__ x) {
    __shared__ float As[KT * STRIDE];
    __shared__ float Bs[KT * STRIDE];

    const int ti = blockIdx.x;        // 0..5
    const int s  = blockIdx.y;        // 0..63
    const int rA = c_TA[ti] * 64;
    const int rB = c_TB[ti] * 64;
    const int b   = s >> 1;
    const int hw0 = (s & 1) * KC;
    const float* xb = x + (size_t)b * CHW + hw0;

    const int tid = threadIdx.x;
    const int my  = tid >> 4;         // 0..15 (row group)
    const int nx  = tid & 15;         // 0..15 (col group)

    float acc[4][4];
#pragma unroll
    for (int i = 0; i < 4; i++)
#pragma unroll
        for (int j = 0; j < 4; j++) acc[i][j] = 0.0f;

    for (int kk = 0; kk < KC; kk += KT) {
        // load 64x32 A-tile and B-tile (transpose into [k][m] layout)
#pragma unroll
        for (int i = 0; i < 2; i++) {
            int e4 = tid + i * 256;           // 0..511
            int m  = e4 >> 3;                 // row in tile
            int k4 = e4 & 7;                  // float4 index within 32 k
            const float4 a = *(const float4*)(xb + (size_t)(rA + m) * HW + kk + 4 * k4);
            const float4 c = *(const float4*)(xb + (size_t)(rB + m) * HW + kk + 4 * k4);
            As[(4 * k4 + 0) * STRIDE + m] = a.x;
            As[(4 * k4 + 1) * STRIDE + m] = a.y;
            As[(4 * k4 + 2) * STRIDE + m] = a.z;
            As[(4 * k4 + 3) * STRIDE + m] = a.w;
            Bs[(4 * k4 + 0) * STRIDE + m] = c.x;
            Bs[(4 * k4 + 1) * STRIDE + m] = c.y;
            Bs[(4 * k4 + 2) * STRIDE + m] = c.z;
            Bs[(4 * k4 + 3) * STRIDE + m] = c.w;
        }
        __syncthreads();
#pragma unroll
        for (int k = 0; k < KT; k++) {
            const float4 a4 = *(const float4*)&As[k * STRIDE + 4 * my];
            const float4 b4 = *(const float4*)&Bs[k * STRIDE + 4 * nx];
            const float av[4] = {a4.x, a4.y, a4.z, a4.w};
            const float bv[4] = {b4.x, b4.y, b4.z, b4.w};
#pragma unroll
            for (int i = 0; i < 4; i++)
#pragma unroll
                for (int j = 0; j < 4; j++)
                    acc[i][j] = fmaf(av[i], bv[j], acc[i][j]);
        }
        __syncthreads();
    }

    float* out = g_partial + ((size_t)s * 6 + ti) * 4096;
#pragma unroll
    for (int i = 0; i < 4; i++)
#pragma unroll
        for (int j = 0; j < 4; j++)
            out[(4 * my + i) * 64 + (4 * nx + j)] = acc[i][j];
}

// ---------------------------------------------------------------------------
// Kernel 2: reduce partials over slices -> symmetric G
// ---------------------------------------------------------------------------
__global__ __launch_bounds__(256) void reduce_kernel() {
    const int gid = blockIdx.x * 256 + threadIdx.x;   // 0..24575
    if (gid >= 6 * 4096) return;
    const int ti = gid >> 12;
    const int r  = gid & 4095;
    const int m  = r >> 6;
    const int nn = r & 63;
    float ssum = 0.0f;
#pragma unroll 8
    for (int s = 0; s < NSLICE; s++)
        ssum += g_partial[((size_t)s * 6 + ti) * 4096 + r];
    const int gi = c_TA[ti] * 64 + m;
    const int gj = c_TB[ti] * 64 + nn;
    g_G[gi * C + gj] = ssum;
    g_G[gj * C + gi] = ssum;
}

// ---------------------------------------------------------------------------
// Kernel 3: D2[i][j] = Gii + Gjj - 2 Gij  (clamped >= 0, diag exactly 0)
// ---------------------------------------------------------------------------
__global__ __launch_bounds__(256) void d2_kernel() {
    const int id = blockIdx.x * 256 + threadIdx.x;
    if (id >= C * C) return;
    const int i = id / C;
    const int j = id % C;
    float d = 0.0f;
    if (i != j) {
        d = g_G[i * C + i] + g_G[j * C + j] - 2.0f * g_G[i * C + j];
        d = fmaxf(d, 0.0f);
    }
    g_D2[id] = d;
}

// ---------------------------------------------------------------------------
// Kernel 4: sequential greedy selection (single block, 96 steps)
// ---------------------------------------------------------------------------
__global__ __launch_bounds__(1024) void select_kernel() {
    __shared__ int sidx[2][C];
    __shared__ unsigned long long warpmin[32];
    __shared__ int s_i, s_j;

    const int tid = threadIdx.x;
    if (tid < C) sidx[0][tid] = tid;
    __syncthreads();

    for (int t = 0; t < T_STEPS; t++) {
        const int cur = t & 1, nxt = cur ^ 1;
        const int n = C - t;
        const int P = n * (n - 1) / 2;

        unsigned long long best = ~0ull;
        for (int pid = tid; pid < P; pid += 1024) {
            // map pid -> (i, j) with j(j-1)/2 <= pid < j(j+1)/2
            int j = (int)((1.0f + sqrtf(8.0f * (float)pid + 1.0f)) * 0.5f);
            while ((j * (j - 1)) / 2 > pid) j--;
            while ((j * (j + 1)) / 2 <= pid) j++;
            const int i = pid - (j * (j - 1)) / 2;
            const int vi = sidx[cur][i];
            const int vj = sidx[cur][j];
            const float d = (vi == vj) ? 0.0f : g_D2[vi * C + vj];
            const unsigned long long key =
                ((unsigned long long)__float_as_uint(d) << 32) |
                (unsigned int)(i * C + j);
            if (key < best) best = key;
        }
#pragma unroll
        for (int o = 16; o > 0; o >>= 1) {
            unsigned long long other = __shfl_down_sync(0xffffffffu, best, o);
            if (other < best) best = other;
        }
        if ((tid & 31) == 0) warpmin[tid >> 5] = best;
        __syncthreads();
        if (tid < 32) {
            best = warpmin[tid];
#pragma unroll
            for (int o = 16; o > 0; o >>= 1) {
                unsigned long long other = __shfl_down_sync(0xffffffffu, best, o);
                if (other < best) best = other;
            }
            if (tid == 0) {
                const int ij = (int)(best & 0xffffffffull);
                const int i = ij / C;
                const int j = ij % C;
                s_i = i; s_j = j;
                g_v1[t] = sidx[cur][i];
                g_v2[t] = sidx[cur][j];
            }
        }
        __syncthreads();
        const int i = s_i, j = s_j;
        if (tid < n && tid != i && tid != j) {
            const int dest = tid - (tid > i) - (tid > j);
            sidx[nxt][dest] = sidx[cur][tid];
        }
        if (tid == 0) sidx[nxt][n - 2] = t;
        __syncthreads();
    }
}

// ---------------------------------------------------------------------------
// Kernel 5: gather + average -> out[b][t][hw]
// ---------------------------------------------------------------------------
__global__ __launch_bounds__(256) void gather_kernel(const float* __restrict__ x,
                                                     float* __restrict__ out) {
    const int t = blockIdx.x;   // 0..95
    const int b = blockIdx.y;   // 0..31
    const int v1 = g_v1[t];
    const int v2 = g_v2[t];
    const float4* p1 = (const float4*)(x + ((size_t)b * C + v1) * HW);
    const float4* p2 = (const float4*)(x + ((size_t)b * C + v2) * HW);
    float4* po = (float4*)(out + ((size_t)b * T_STEPS + t) * HW);
    for (int q = threadIdx.x; q < HW / 4; q += blockDim.x) {
        const float4 a = p1[q];
        const float4 c = p2[q];
        float4 r;
        r.x = 0.5f * (a.x + c.x);
        r.y = 0.5f * (a.y + c.y);
        r.z = 0.5f * (a.z + c.z);
        r.w = 0.5f * (a.w + c.w);
        po[q] = r;
    }
}

// ---------------------------------------------------------------------------
extern "C" void kernel_launch(void* const* d_in, const int* in_sizes, int n_in,
                              void* d_out, int out_size) {
    const float* x = (const float*)d_in[0];
    float* out = (float*)d_out;

    gram_kernel<<<dim3(6, NSLICE), 256>>>(x);
    reduce_kernel<<<96, 256>>>();
    d2_kernel<<<144, 256>>>();
    select_kernel<<<1, 1024>>>();
    gather_kernel<<<dim3(T_STEPS, BATCH), 256>>>(x, out);
}

// round 2
// speedup vs baseline: 1.4928x; 1.4928x over previous
#include <cuda_runtime.h>
#include <cuda_bf16.h>
#include <cstdint>

// Problem constants
#define BATCH 32
#define C     192
#define HW    3136            // 56*56
#define CHW   602112          // C*HW
#define T_STEPS 96
#define NSLICE 64             // K-slices for gram GEMM (2 per batch image)
#define KC    1568            // K per slice (HW/2)
#define KT    32              // k-tile
#define STRIDE 68             // padded smem row stride (multiple of 4 for float4)

#define SMEM_D2_BYTES (C * C * 4)   // 147456

// Static device scratch (no allocations allowed)
__device__ float g_partial[NSLICE * 6 * 64 * 64];   // 6 MB
__device__ float g_G[C * C];
__device__ int   g_v1[T_STEPS];
__device__ int   g_v2[T_STEPS];

__constant__ int c_TA[6] = {0, 0, 0, 1, 1, 2};
__constant__ int c_TB[6] = {0, 1, 2, 1, 2, 2};

// ---------------------------------------------------------------------------
// Kernel 1: partial Gram.  Block (ti, s): 64x64 tile ti over K-slice s.
// ---------------------------------------------------------------------------
__global__ __launch_bounds__(256) void gram_kernel(const float* __restrict__ x) {
    __shared__ float As[KT * STRIDE];
    __shared__ float Bs[KT * STRIDE];

    const int ti = blockIdx.x;        // 0..5
    const int s  = blockIdx.y;        // 0..63
    const int rA = c_TA[ti] * 64;
    const int rB = c_TB[ti] * 64;
    const int b   = s >> 1;
    const int hw0 = (s & 1) * KC;
    const float* xb = x + (size_t)b * CHW + hw0;

    const int tid = threadIdx.x;
    const int my  = tid >> 4;         // 0..15 (row group)
    const int nx  = tid & 15;         // 0..15 (col group)

    float acc[4][4];
#pragma unroll
    for (int i = 0; i < 4; i++)
#pragma unroll
        for (int j = 0; j < 4; j++) acc[i][j] = 0.0f;

    for (int kk = 0; kk < KC; kk += KT) {
        // load 64x32 A-tile and B-tile (transpose into [k][m] layout)
#pragma unroll
        for (int i = 0; i < 2; i++) {
            int e4 = tid + i * 256;           // 0..511
            int m  = e4 >> 3;                 // row in tile
            int k4 = e4 & 7;                  // float4 index within 32 k
            const float4 a = *(const float4*)(xb + (size_t)(rA + m) * HW + kk + 4 * k4);
            const float4 c = *(const float4*)(xb + (size_t)(rB + m) * HW + kk + 4 * k4);
            As[(4 * k4 + 0) * STRIDE + m] = a.x;
            As[(4 * k4 + 1) * STRIDE + m] = a.y;
            As[(4 * k4 + 2) * STRIDE + m] = a.z;
            As[(4 * k4 + 3) * STRIDE + m] = a.w;
            Bs[(4 * k4 + 0) * STRIDE + m] = c.x;
            Bs[(4 * k4 + 1) * STRIDE + m] = c.y;
            Bs[(4 * k4 + 2) * STRIDE + m] = c.z;
            Bs[(4 * k4 + 3) * STRIDE + m] = c.w;
        }
        __syncthreads();
#pragma unroll
        for (int k = 0; k < KT; k++) {
            const float4 a4 = *(const float4*)&As[k * STRIDE + 4 * my];
            const float4 b4 = *(const float4*)&Bs[k * STRIDE + 4 * nx];
            const float av[4] = {a4.x, a4.y, a4.z, a4.w};
            const float bv[4] = {b4.x, b4.y, b4.z, b4.w};
#pragma unroll
            for (int i = 0; i < 4; i++)
#pragma unroll
                for (int j = 0; j < 4; j++)
                    acc[i][j] = fmaf(av[i], bv[j], acc[i][j]);
        }
        __syncthreads();
    }

    float* out = g_partial + ((size_t)s * 6 + ti) * 4096;
#pragma unroll
    for (int i = 0; i < 4; i++)
#pragma unroll
        for (int j = 0; j < 4; j++)
            out[(4 * my + i) * 64 + (4 * nx + j)] = acc[i][j];
}

// ---------------------------------------------------------------------------
// Kernel 2: reduce partials over slices -> symmetric G
// ---------------------------------------------------------------------------
__global__ __launch_bounds__(256) void reduce_kernel() {
    const int gid = blockIdx.x * 256 + threadIdx.x;   // 0..24575
    if (gid >= 6 * 4096) return;
    const int ti = gid >> 12;
    const int r  = gid & 4095;
    const int m  = r >> 6;
    const int nn = r & 63;
    float ssum = 0.0f;
#pragma unroll 8
    for (int s = 0; s < NSLICE; s++)
        ssum += g_partial[((size_t)s * 6 + ti) * 4096 + r];
    const int gi = c_TA[ti] * 64 + m;
    const int gj = c_TB[ti] * 64 + nn;
    g_G[gi * C + gj] = ssum;
    g_G[gj * C + gi] = ssum;
}

// ---------------------------------------------------------------------------
// Kernel 3: sequential greedy selection (single block, 96 steps).
// D2 lives in shared memory (144KB); rectangular pid->(i,j) mapping with
// compile-time divisor (no sqrt, no while loops). Tie-break identical to
// row-major first-occurrence argmin: key low bits = i*C + j.
// ---------------------------------------------------------------------------
__global__ __launch_bounds__(1024) void select_kernel() {
    extern __shared__ float sD2[];              // C*C floats
    __shared__ int sidx[2][C];
    __shared__ unsigned long long warpmin[32];
    __shared__ int s_ij;

    const int tid = threadIdx.x;

    // Prologue: build D2 in shared memory from Gram matrix (fused d2_kernel).
    for (int id = tid; id < C * C; id += 1024) {
        const int i = id / C;
        const int j = id - i * C;
        float d = 0.0f;
        if (i != j) {
            d = g_G[i * C + i] + g_G[j * C + j] - 2.0f * g_G[i * C + j];
            d = fmaxf(d, 0.0f);
        }
        sD2[id] = d;
    }
    if (tid < C) sidx[0][tid] = tid;
    __syncthreads();

    for (int t = 0; t < T_STEPS; t++) {
        const int cur = t & 1, nxt = cur ^ 1;
        const int n = C - t;
        const int total = n * C;                // covers all i in [0,n), j in [0,C)

        unsigned long long best = ~0ull;
        for (int pid = tid; pid < total; pid += 1024) {
            const int i = pid / C;              // compile-time divisor -> IMAD
            const int j = pid - i * C;
            if (j > i && j < n) {
                const int vi = sidx[cur][i];
                const int vj = sidx[cur][j];
                const float d = sD2[vi * C + vj];   // diag==0 handles dup ids
                const unsigned long long key =
                    ((unsigned long long)__float_as_uint(d) << 32) |
                    (unsigned int)pid;
                if (key < best) best = key;
            }
        }
#pragma unroll
        for (int o = 16; o > 0; o >>= 1) {
            unsigned long long other = __shfl_down_sync(0xffffffffu, best, o);
            if (other < best) best = other;
        }
        if ((tid & 31) == 0) warpmin[tid >> 5] = best;
        __syncthreads();
        if (tid < 32) {
            best = warpmin[tid];
#pragma unroll
            for (int o = 16; o > 0; o >>= 1) {
                unsigned long long other = __shfl_down_sync(0xffffffffu, best, o);
                if (other < best) best = other;
            }
            if (tid == 0) {
                const int ij = (int)(best & 0xffffffffull);
                s_ij = ij;
                const int i = ij / C;
                const int j = ij - i * C;
                g_v1[t] = sidx[cur][i];
                g_v2[t] = sidx[cur][j];
            }
        }
        __syncthreads();
        const int ij = s_ij;
        const int i = ij / C;
        const int j = ij - i * C;
        if (tid < n && tid != i && tid != j) {
            const int dest = tid - (tid > i) - (tid > j);
            sidx[nxt][dest] = sidx[cur][tid];
        }
        if (tid == 0) sidx[nxt][n - 2] = t;
        __syncthreads();
    }
}

// ---------------------------------------------------------------------------
// Kernel 4: gather + average -> out[b][t][hw]
// ---------------------------------------------------------------------------
__global__ __launch_bounds__(256) void gather_kernel(const float* __restrict__ x,
                                                     float* __restrict__ out) {
    const int t = blockIdx.x;   // 0..95
    const int b = blockIdx.y;   // 0..31
    const int v1 = g_v1[t];
    const int v2 = g_v2[t];
    const float4* p1 = (const float4*)(x + ((size_t)b * C + v1) * HW);
    const float4* p2 = (const float4*)(x + ((size_t)b * C + v2) * HW);
    float4* po = (float4*)(out + ((size_t)b * T_STEPS + t) * HW);
    for (int q = threadIdx.x; q < HW / 4; q += blockDim.x) {
        const float4 a = p1[q];
        const float4 c = p2[q];
        float4 r;
        r.x = 0.5f * (a.x + c.x);
        r.y = 0.5f * (a.y + c.y);
        r.z = 0.5f * (a.z + c.z);
        r.w = 0.5f * (a.w + c.w);
        po[q] = r;
    }
}

// ---------------------------------------------------------------------------
extern "C" void kernel_launch(void* const* d_in, const int* in_sizes, int n_in,
                              void* d_out, int out_size) {
    const float* x = (const float*)d_in[0];
    float* out = (float*)d_out;

    static bool attr_set = false;
    if (!attr_set) {
        cudaFuncSetAttribute(select_kernel,
                             cudaFuncAttributeMaxDynamicSharedMemorySize,
                             SMEM_D2_BYTES);
        attr_set = true;
    }

    gram_kernel<<<dim3(6, NSLICE), 256>>>(x);
    reduce_kernel<<<96, 256>>>();
    select_kernel<<<1, 1024, SMEM_D2_BYTES>>>();
    gather_kernel<<<dim3(T_STEPS, BATCH), 256>>>(x, out);
}